// round 16
// baseline (speedup 1.0000x reference)
#include <cuda_runtime.h>
#include <cuda_fp16.h>
#include <cstdint>

#define E_TOT    131072
#define DDIM     128
#define KTOT     2048
#define TILE_E   64
#define NTHREADS 256
#define NCHUNKS  64

// ---- SMEM byte offsets ----
#define UV_OFF   0             // chunk-major: 64 chunks * 64 rows * 8B = 32768
#define S3_OFF   32768         // 128 f
#define Q3_OFF   33280
#define CA_OFF   33792         // 16 f
#define CB_OFF   33856
#define CD_OFF   33920
#define ROW_OFF  33984         // 64 i
#define COL_OFF  34240
#define TYP_OFF  34496
#define DS_OFF   34752         // 4 * 64 f = 1024
#define SMEM_BYTES 36864

// Weight A-fragments (m16n8k16 A operand), fragment-major:
// [chunk][s][nb16][lane] as uint4 = (a0,a1,a2,a3)
//   g=lane>>2, t=lane&3, j=chunk*2+s, n0=nb16*16+g, n1=n0+8
//   a0={W[2t][n0],W[2t+1][n0]}  a1={W[2t][n1],W[2t+1][n1]}
//   a2={W[8+2t][n0],W[9+2t][n0]} a3={W[8+2t][n1],W[9+2t][n1]}
//   where W[c][n] = fc_w[c*128+j][n]
__device__ uint4 g_Ah[NCHUNKS * 2 * 8 * 32];

__device__ __forceinline__ void mma_f16(float* c, uint32_t a0, uint32_t a1,
                                        uint32_t a2, uint32_t a3,
                                        uint32_t b0, uint32_t b1) {
    asm volatile(
        "mma.sync.aligned.m16n8k16.row.col.f32.f16.f16.f32 "
        "{%0,%1,%2,%3}, {%4,%5,%6,%7}, {%8,%9}, {%0,%1,%2,%3};"
        : "+f"(c[0]), "+f"(c[1]), "+f"(c[2]), "+f"(c[3])
        : "r"(a0), "r"(a1), "r"(a2), "r"(a3), "r"(b0), "r"(b1));
}
__device__ __forceinline__ uint32_t h2u(__half2 x) { return *(uint32_t*)&x; }
__device__ __forceinline__ __half2 u2h(uint32_t x) { return *(__half2*)&x; }

// ===== prep: weight A-fragments from fc_w =====
extern "C" __global__ void conve_prep(const float* __restrict__ fc_w)
{
    const int idx = blockIdx.x * 256 + threadIdx.x;   // 0..32767
    const int lane = idx & 31;
    const int nb16 = (idx >> 5) & 7;
    const int s    = (idx >> 8) & 1;
    const int chunk = idx >> 9;
    const int g = lane >> 2;
    const int t = lane & 3;
    const int j = chunk * 2 + s;
    const int n0 = nb16 * 16 + g;
    const int n1 = n0 + 8;
    const int c0 = 2 * t, c1 = 2 * t + 1, c2 = 8 + 2 * t, c3 = 9 + 2 * t;

    __half2 a0 = __floats2half2_rn(fc_w[(long)(c0 * 128 + j) * DDIM + n0],
                                   fc_w[(long)(c1 * 128 + j) * DDIM + n0]);
    __half2 a1 = __floats2half2_rn(fc_w[(long)(c0 * 128 + j) * DDIM + n1],
                                   fc_w[(long)(c1 * 128 + j) * DDIM + n1]);
    __half2 a2 = __floats2half2_rn(fc_w[(long)(c2 * 128 + j) * DDIM + n0],
                                   fc_w[(long)(c3 * 128 + j) * DDIM + n0]);
    __half2 a3 = __floats2half2_rn(fc_w[(long)(c2 * 128 + j) * DDIM + n1],
                                   fc_w[(long)(c3 * 128 + j) * DDIM + n1]);
    uint4 v;
    v.x = h2u(a0); v.y = h2u(a1); v.z = h2u(a2); v.w = h2u(a3);
    g_Ah[idx] = v;
}

// ===== main: 2 CTAs/SM, 8 warps (4 n-groups x 2 e-groups), weights-in-A =====
extern "C" __global__ void __launch_bounds__(NTHREADS, 2)
conve_main(const float* __restrict__ h, const float* __restrict__ g,
           const int* __restrict__ eidx, const int* __restrict__ etype,
           const float* __restrict__ conv_w, const float* __restrict__ conv_b,
           const float* __restrict__ fc_b,
           const float* __restrict__ bn1g, const float* __restrict__ bn1b,
           const float* __restrict__ bn1m, const float* __restrict__ bn1v,
           const float* __restrict__ bn3g, const float* __restrict__ bn3b,
           const float* __restrict__ bn3m, const float* __restrict__ bn3v,
           float* __restrict__ out)
{
    extern __shared__ char smc[];
    uint2* UV = (uint2*)(smc + UV_OFF);   // UV[chunk*64 + row]
    float* S3 = (float*)(smc + S3_OFF);
    float* Q3 = (float*)(smc + Q3_OFF);
    float* CA = (float*)(smc + CA_OFF);
    float* CB = (float*)(smc + CB_OFF);
    float* CD = (float*)(smc + CD_OFF);
    int* ROW = (int*)(smc + ROW_OFF);
    int* COL = (int*)(smc + COL_OFF);
    int* TYP = (int*)(smc + TYP_OFF);

    const int tid  = threadIdx.x;
    const int wid  = tid >> 5;
    const int lane = tid & 31;
    const int gid  = lane >> 2;
    const int tig  = lane & 3;
    const int e0   = blockIdx.x * TILE_E;

    if (tid < DDIM) {
        float s = bn3g[tid] * rsqrtf(bn3v[tid] + 1e-5f);
        S3[tid] = s;
        Q3[tid] = fc_b[tid] * s + bn3b[tid] - bn3m[tid] * s;
    }
    if (tid < TILE_E) {
        ROW[tid] = eidx[e0 + tid];
        COL[tid] = eidx[E_TOT + e0 + tid];
        TYP[tid] = etype[e0 + tid];
    }
    if (tid < 16) {
        float s1 = bn1g[0] * rsqrtf(bn1v[0] + 1e-5f);
        float b1 = bn1b[0] - bn1m[0] * s1;
        float w0 = conv_w[tid * 2], w1 = conv_w[tid * 2 + 1];
        CA[tid] = w0 * s1;
        CB[tid] = w1 * s1;
        CD[tid] = (w0 + w1) * b1 + conv_b[tid];
    }
    __syncthreads();

    // ---- gather h[row], g[type] -> chunk-major fp16 SMEM UV[chunk][row] ----
    {
        const int row = tid >> 2;
        const int jq  = tid & 3;            // 32 j-values each
        const float* hp = h + (long)ROW[row] * DDIM + jq * 32;
        const float* gp = g + (long)TYP[row] * DDIM + jq * 32;
#pragma unroll
        for (int i = 0; i < 8; i++) {
            const float4 fu = __ldg((const float4*)(hp + i * 4));
            const float4 fv = __ldg((const float4*)(gp + i * 4));
            const int ch = jq * 16 + i * 2;
            UV[ch * 64 + row] =
                make_uint2(h2u(__floats2half2_rn(fu.x, fu.y)),
                           h2u(__floats2half2_rn(fv.x, fv.y)));
            UV[(ch + 1) * 64 + row] =
                make_uint2(h2u(__floats2half2_rn(fu.z, fu.w)),
                           h2u(__floats2half2_rn(fv.z, fv.w)));
        }
    }
    __syncthreads();

    // ---- per-lane channel-pair coefficients (half2) ----
    __half2 ca2[2], cb2[2], cd2[2];
#pragma unroll
    for (int p = 0; p < 2; p++) {
        const int c = p * 8 + 2 * tig;
        ca2[p] = __floats2half2_rn(CA[c], CA[c + 1]);
        cb2[p] = __floats2half2_rn(CB[c], CB[c + 1]);
        cd2[p] = __floats2half2_rn(CD[c], CD[c + 1]);
    }
    const __half2 zero2 = __floats2half2_rn(0.0f, 0.0f);

    // warp grid: eg = wid&1 (32-edge group), nq = wid>>1 (32-n group)
    const int eg = wid & 1;
    const int nq = wid >> 1;
    const int ebase = eg * 32;
    const int nbase = nq * 32;

    float acc[2][4][4];    // [mt(n16)][et(e8)][q]
#pragma unroll
    for (int mt = 0; mt < 2; mt++)
#pragma unroll
        for (int et = 0; et < 4; et++)
#pragma unroll
            for (int q = 0; q < 4; q++) acc[mt][et][q] = 0.0f;

    // ---- weight A-frags: in-place s-step sets, refilled after use ----
    // Ap(chunk, s, mt) = g_Ah[((chunk*2+s)*8 + nq*2+mt)*32 + lane]
    const uint4* Ap = g_Ah + (nq * 2) * 32 + lane;
    uint4 P0[2], P1[2];
#pragma unroll
    for (int mt = 0; mt < 2; mt++) P0[mt] = __ldg(Ap + mt * 32);          // c0,s0
#pragma unroll
    for (int mt = 0; mt < 2; mt++) P1[mt] = __ldg(Ap + 256 + mt * 32);    // c0,s1

    // ---- u/v: prefetch chunk 0 (rows ebase + et*8 + gid) ----
    uint2 uv[4], uvn[4];
#pragma unroll
    for (int et = 0; et < 4; et++)
        uv[et] = UV[ebase + et * 8 + gid];

    for (int chunk = 0; chunk < NCHUNKS; chunk++) {
        const int last = (chunk == NCHUNKS - 1);
        if (!last) {
            const uint2* uvp = UV + (chunk + 1) * 64 + ebase + gid;
#pragma unroll
            for (int et = 0; et < 4; et++)
                uvn[et] = uvp[et * 8];
        }

        // ---- s = 0 ----
        {
            uint32_t flo[4], fhi[4];
#pragma unroll
            for (int et = 0; et < 4; et++) {
                const __half2 uu = __low2half2(u2h(uv[et].x));
                const __half2 vv = __low2half2(u2h(uv[et].y));
                __half2 t0 = __hfma2(cb2[0], vv, cd2[0]);
                __half2 t1 = __hfma2(cb2[1], vv, cd2[1]);
                t0 = __hmax2(__hfma2(ca2[0], uu, t0), zero2);
                t1 = __hmax2(__hfma2(ca2[1], uu, t1), zero2);
                flo[et] = h2u(t0);
                fhi[et] = h2u(t1);
            }
#pragma unroll
            for (int et = 0; et < 4; et++) {
                mma_f16(acc[0][et], P0[0].x, P0[0].y, P0[0].z, P0[0].w,
                        flo[et], fhi[et]);
                mma_f16(acc[1][et], P0[1].x, P0[1].y, P0[1].z, P0[1].w,
                        flo[et], fhi[et]);
            }
            if (!last) {
                const uint4* an = Ap + (chunk + 1) * 512;
#pragma unroll
                for (int mt = 0; mt < 2; mt++) P0[mt] = __ldg(an + mt * 32);
            }
        }
        // ---- s = 1 ----
        {
            uint32_t flo[4], fhi[4];
#pragma unroll
            for (int et = 0; et < 4; et++) {
                const __half2 uu = __high2half2(u2h(uv[et].x));
                const __half2 vv = __high2half2(u2h(uv[et].y));
                __half2 t0 = __hfma2(cb2[0], vv, cd2[0]);
                __half2 t1 = __hfma2(cb2[1], vv, cd2[1]);
                t0 = __hmax2(__hfma2(ca2[0], uu, t0), zero2);
                t1 = __hmax2(__hfma2(ca2[1], uu, t1), zero2);
                flo[et] = h2u(t0);
                fhi[et] = h2u(t1);
            }
#pragma unroll
            for (int et = 0; et < 4; et++) {
                mma_f16(acc[0][et], P1[0].x, P1[0].y, P1[0].z, P1[0].w,
                        flo[et], fhi[et]);
                mma_f16(acc[1][et], P1[1].x, P1[1].y, P1[1].z, P1[1].w,
                        flo[et], fhi[et]);
            }
            if (!last) {
                const uint4* an = Ap + (chunk + 1) * 512 + 256;
#pragma unroll
                for (int mt = 0; mt < 2; mt++) P1[mt] = __ldg(an + mt * 32);
            }
        }
#pragma unroll
        for (int et = 0; et < 4; et++) uv[et] = uvn[et];
    }

    // ---- epilogue: D rows = n, cols = edges (2tig, 2tig+1) ----
    float dote[4][2];
#pragma unroll
    for (int et = 0; et < 4; et++) { dote[et][0] = 0.f; dote[et][1] = 0.f; }

#pragma unroll
    for (int et = 0; et < 4; et++) {
        const int ee0 = ebase + et * 8 + 2 * tig;
        const float* c0p = h + (long)COL[ee0] * DDIM;
        const float* c1p = h + (long)COL[ee0 + 1] * DDIM;
#pragma unroll
        for (int mt = 0; mt < 2; mt++) {
            const int n0 = nbase + mt * 16 + gid;
            const int n1 = n0 + 8;
            const float s30 = S3[n0], q30 = Q3[n0];
            const float s31 = S3[n1], q31 = Q3[n1];
            const float z00 = fmaxf(fmaf(acc[mt][et][0], s30, q30), 0.0f); // [n0][e0]
            const float z01 = fmaxf(fmaf(acc[mt][et][1], s30, q30), 0.0f); // [n0][e1]
            const float z10 = fmaxf(fmaf(acc[mt][et][2], s31, q31), 0.0f); // [n1][e0]
            const float z11 = fmaxf(fmaf(acc[mt][et][3], s31, q31), 0.0f); // [n1][e1]
            dote[et][0] = fmaf(z00, __ldg(c0p + n0), fmaf(z10, __ldg(c0p + n1), dote[et][0]));
            dote[et][1] = fmaf(z01, __ldg(c1p + n0), fmaf(z11, __ldg(c1p + n1), dote[et][1]));
        }
    }

    float* dsum = (float*)(smc + DS_OFF);
#pragma unroll
    for (int et = 0; et < 4; et++) {
#pragma unroll
        for (int par = 0; par < 2; par++) {
            float v = dote[et][par];
            v += __shfl_xor_sync(0xffffffffu, v, 4);
            v += __shfl_xor_sync(0xffffffffu, v, 8);
            v += __shfl_xor_sync(0xffffffffu, v, 16);
            if (gid == 0)
                dsum[nq * TILE_E + ebase + et * 8 + 2 * tig + par] = v;
        }
    }
    __syncthreads();
    if (tid < TILE_E) {
        const float* ds = (const float*)(smc + DS_OFF);
        out[e0 + tid] = (ds[tid] + ds[TILE_E + tid]) +
                        (ds[2 * TILE_E + tid] + ds[3 * TILE_E + tid]);
    }
}

// ===== launch =====
extern "C" void kernel_launch(void* const* d_in, const int* in_sizes, int n_in,
                              void* d_out, int out_size)
{
    const float* h      = (const float*)d_in[0];
    const float* g      = (const float*)d_in[1];
    const int*   eidx   = (const int*)d_in[2];
    const int*   etype  = (const int*)d_in[3];
    const float* conv_w = (const float*)d_in[4];
    const float* conv_b = (const float*)d_in[5];
    const float* fc_w   = (const float*)d_in[6];
    const float* fc_b   = (const float*)d_in[7];
    const float* bn1g   = (const float*)d_in[8];
    const float* bn1b   = (const float*)d_in[9];
    const float* bn1m   = (const float*)d_in[10];
    const float* bn1v   = (const float*)d_in[11];
    const float* bn3g   = (const float*)d_in[12];
    const float* bn3b   = (const float*)d_in[13];
    const float* bn3m   = (const float*)d_in[14];
    const float* bn3v   = (const float*)d_in[15];
    float* out = (float*)d_out;

    conve_prep<<<128, 256>>>(fc_w);   // 32768 A-fragment uint4s

    cudaFuncSetAttribute(conve_main,
                         cudaFuncAttributeMaxDynamicSharedMemorySize, SMEM_BYTES);
    conve_main<<<E_TOT / TILE_E, NTHREADS, SMEM_BYTES>>>(
        h, g, eidx, etype, conv_w, conv_b, fc_b,
        bn1g, bn1b, bn1m, bn1v, bn3g, bn3b, bn3m, bn3v, out);
}

// round 17
// speedup vs baseline: 1.0118x; 1.0118x over previous
#include <cuda_runtime.h>
#include <cuda_fp16.h>
#include <cstdint>

#define E_TOT    131072
#define DDIM     128
#define KTOT     2048
#define TILE_E   32
#define NTHREADS 256
#define NCHUNKS  64

// ---- SMEM byte offsets ----
#define UV_OFF   0             // chunk-major: 64 chunks * 32 rows * 8B = 16384
#define S3_OFF   16384         // 128 f
#define Q3_OFF   16896
#define CA_OFF   17408         // 16 f
#define CB_OFF   17472
#define CD_OFF   17536
#define ROW_OFF  17600         // 32 i
#define COL_OFF  17728
#define TYP_OFF  17856
#define DS_OFF   17984         // 4 * 32 f = 512
#define SMEM_BYTES 18688

// fc_w in fp16, fragment-major: [chunk][s][nblk][lane] * 4 halves (8B units)
// lane = gid*4+tig; halves = {B[c=2tig][n], B[2tig+1][n], B[8+2tig][n], B[9+2tig][n]}
// n = nblk*8+gid; j = chunk*2+s; klog = c*128+j      (identical to R8-R15, proven)
__device__ __half g_Bh[NCHUNKS * 2 * 16 * 32 * 4];

__device__ __forceinline__ void mma_f16(float* c, uint32_t a0, uint32_t a1,
                                        uint32_t a2, uint32_t a3,
                                        uint32_t b0, uint32_t b1) {
    asm volatile(
        "mma.sync.aligned.m16n8k16.row.col.f32.f16.f16.f32 "
        "{%0,%1,%2,%3}, {%4,%5,%6,%7}, {%8,%9}, {%0,%1,%2,%3};"
        : "+f"(c[0]), "+f"(c[1]), "+f"(c[2]), "+f"(c[3])
        : "r"(a0), "r"(a1), "r"(a2), "r"(a3), "r"(b0), "r"(b1));
}
__device__ __forceinline__ uint32_t h2u(__half2 x) { return *(uint32_t*)&x; }
__device__ __forceinline__ __half2 u2h(uint32_t x) { return *(__half2*)&x; }

// ===== prep: fragment-major fp16 B from fc_w (identical to R8-R15, proven) =====
extern "C" __global__ void conve_prep(const float* __restrict__ fc_w)
{
    const int idx = blockIdx.x * 256 + threadIdx.x;     // 0..65535 (8B units)
    const int lane  = idx & 31;
    const int nblk  = (idx >> 5) & 15;
    const int s     = (idx >> 9) & 1;
    const int chunk = idx >> 10;
    const int gid = lane >> 2;
    const int tig = lane & 3;
    const int n = nblk * 8 + gid;
    const int j = chunk * 2 + s;

    const int c0 = 2 * tig, c1 = 2 * tig + 1, c2 = 8 + 2 * tig, c3 = 9 + 2 * tig;
    float f0 = fc_w[(long)(c0 * 128 + j) * DDIM + n];
    float f1 = fc_w[(long)(c1 * 128 + j) * DDIM + n];
    float f2 = fc_w[(long)(c2 * 128 + j) * DDIM + n];
    float f3 = fc_w[(long)(c3 * 128 + j) * DDIM + n];
    __half2* dst = (__half2*)(g_Bh + (long)idx * 4);
    dst[0] = __floats2half2_rn(f0, f1);
    dst[1] = __floats2half2_rn(f2, f3);
}

// ===== main: 3 CTAs/SM, 8 warps in 2m x 4n grid (16m x 32n per warp) =====
extern "C" __global__ void __launch_bounds__(NTHREADS, 3)
conve_main(const float* __restrict__ h, const float* __restrict__ g,
           const int* __restrict__ eidx, const int* __restrict__ etype,
           const float* __restrict__ conv_w, const float* __restrict__ conv_b,
           const float* __restrict__ fc_b,
           const float* __restrict__ bn1g, const float* __restrict__ bn1b,
           const float* __restrict__ bn1m, const float* __restrict__ bn1v,
           const float* __restrict__ bn3g, const float* __restrict__ bn3b,
           const float* __restrict__ bn3m, const float* __restrict__ bn3v,
           float* __restrict__ out)
{
    extern __shared__ char smc[];
    uint2* UV = (uint2*)(smc + UV_OFF);   // UV[chunk*32 + row]
    float* S3 = (float*)(smc + S3_OFF);
    float* Q3 = (float*)(smc + Q3_OFF);
    float* CA = (float*)(smc + CA_OFF);
    float* CB = (float*)(smc + CB_OFF);
    float* CD = (float*)(smc + CD_OFF);
    int* ROW = (int*)(smc + ROW_OFF);
    int* COL = (int*)(smc + COL_OFF);
    int* TYP = (int*)(smc + TYP_OFF);

    const int tid  = threadIdx.x;
    const int wid  = tid >> 5;
    const int lane = tid & 31;
    const int gid  = lane >> 2;
    const int tig  = lane & 3;
    const int e0   = blockIdx.x * TILE_E;

    if (tid < DDIM) {
        float s = bn3g[tid] * rsqrtf(bn3v[tid] + 1e-5f);
        S3[tid] = s;
        Q3[tid] = fc_b[tid] * s + bn3b[tid] - bn3m[tid] * s;
    }
    if (tid < TILE_E) {
        ROW[tid] = eidx[e0 + tid];
        COL[tid] = eidx[E_TOT + e0 + tid];
        TYP[tid] = etype[e0 + tid];
    }
    if (tid < 16) {
        float s1 = bn1g[0] * rsqrtf(bn1v[0] + 1e-5f);
        float b1 = bn1b[0] - bn1m[0] * s1;
        float w0 = conv_w[tid * 2], w1 = conv_w[tid * 2 + 1];
        CA[tid] = w0 * s1;
        CB[tid] = w1 * s1;
        CD[tid] = (w0 + w1) * b1 + conv_b[tid];
    }
    __syncthreads();

    // ---- gather h[row], g[type] -> chunk-major fp16 SMEM UV[chunk][row] ----
    {
        const int row = tid >> 3;           // 0..31
        const int jq  = tid & 7;            // 16 j-values each
        const float* hp = h + (long)ROW[row] * DDIM + jq * 16;
        const float* gp = g + (long)TYP[row] * DDIM + jq * 16;
#pragma unroll
        for (int i = 0; i < 4; i++) {
            const float4 fu = __ldg((const float4*)(hp + i * 4));
            const float4 fv = __ldg((const float4*)(gp + i * 4));
            const int ch = jq * 8 + i * 2;
            UV[ch * 32 + row] =
                make_uint2(h2u(__floats2half2_rn(fu.x, fu.y)),
                           h2u(__floats2half2_rn(fv.x, fv.y)));
            UV[(ch + 1) * 32 + row] =
                make_uint2(h2u(__floats2half2_rn(fu.z, fu.w)),
                           h2u(__floats2half2_rn(fv.z, fv.w)));
        }
    }
    __syncthreads();

    // ---- per-lane channel-pair coefficients (half2) ----
    __half2 ca2[2], cb2[2], cd2[2];
#pragma unroll
    for (int p = 0; p < 2; p++) {
        const int c = p * 8 + 2 * tig;
        ca2[p] = __floats2half2_rn(CA[c], CA[c + 1]);
        cb2[p] = __floats2half2_rn(CB[c], CB[c + 1]);
        cd2[p] = __floats2half2_rn(CD[c], CD[c + 1]);
    }
    const __half2 zero2 = __floats2half2_rn(0.0f, 0.0f);

    // 2m x 4n warp grid: eg = wid&1 (16 rows), nq = wid>>1 (32 n)
    const int eg = wid & 1;
    const int nq = wid >> 1;
    const int ebase = eg * 16;
    const int nblk0 = nq * 4;
    const int r0    = ebase + gid;

    float acc[4][4];
#pragma unroll
    for (int nt = 0; nt < 4; nt++)
#pragma unroll
        for (int q = 0; q < 4; q++) acc[nt][q] = 0.0f;

    // ---- B fragments: in-place s-step sets, refilled after use ----
    const uint2* Bp = (const uint2*)g_Bh + nblk0 * 32 + lane;
    uint2 P0[4], P1[4];
#pragma unroll
    for (int nt = 0; nt < 4; nt++) P0[nt] = __ldg(Bp + nt * 32);         // c0,s0
#pragma unroll
    for (int nt = 0; nt < 4; nt++) P1[nt] = __ldg(Bp + 512 + nt * 32);   // c0,s1

    // ---- u/v: prefetch chunk 0 ----
    uint2 uv[2], uvn[2];
#pragma unroll
    for (int q = 0; q < 2; q++)
        uv[q] = UV[r0 + q * 8];

    for (int chunk = 0; chunk < NCHUNKS; chunk++) {
        const int last = (chunk == NCHUNKS - 1);
        if (!last) {
            const uint2* uvp = UV + (chunk + 1) * 32 + r0;
#pragma unroll
            for (int q = 0; q < 2; q++)
                uvn[q] = uvp[q * 8];
        }

        // ---- s = 0 ----
        {
            uint32_t flo[2], fhi[2];
#pragma unroll
            for (int q = 0; q < 2; q++) {
                const __half2 uu = __low2half2(u2h(uv[q].x));
                const __half2 vv = __low2half2(u2h(uv[q].y));
                __half2 t0 = __hfma2(cb2[0], vv, cd2[0]);
                __half2 t1 = __hfma2(cb2[1], vv, cd2[1]);
                t0 = __hmax2(__hfma2(ca2[0], uu, t0), zero2);
                t1 = __hmax2(__hfma2(ca2[1], uu, t1), zero2);
                flo[q] = h2u(t0);
                fhi[q] = h2u(t1);
            }
#pragma unroll
            for (int nt = 0; nt < 4; nt++)
                mma_f16(acc[nt], flo[0], flo[1], fhi[0], fhi[1],
                        P0[nt].x, P0[nt].y);
            if (!last) {
                const uint2* bn = Bp + (chunk + 1) * 1024;
#pragma unroll
                for (int nt = 0; nt < 4; nt++) P0[nt] = __ldg(bn + nt * 32);
            }
        }
        // ---- s = 1 ----
        {
            uint32_t flo[2], fhi[2];
#pragma unroll
            for (int q = 0; q < 2; q++) {
                const __half2 uu = __high2half2(u2h(uv[q].x));
                const __half2 vv = __high2half2(u2h(uv[q].y));
                __half2 t0 = __hfma2(cb2[0], vv, cd2[0]);
                __half2 t1 = __hfma2(cb2[1], vv, cd2[1]);
                t0 = __hmax2(__hfma2(ca2[0], uu, t0), zero2);
                t1 = __hmax2(__hfma2(ca2[1], uu, t1), zero2);
                flo[q] = h2u(t0);
                fhi[q] = h2u(t1);
            }
#pragma unroll
            for (int nt = 0; nt < 4; nt++)
                mma_f16(acc[nt], flo[0], flo[1], fhi[0], fhi[1],
                        P1[nt].x, P1[nt].y);
            if (!last) {
                const uint2* bn = Bp + (chunk + 1) * 1024 + 512;
#pragma unroll
                for (int nt = 0; nt < 4; nt++) P1[nt] = __ldg(bn + nt * 32);
            }
        }
#pragma unroll
        for (int q = 0; q < 2; q++) uv[q] = uvn[q];
    }

    // ---- epilogue: bn3 + relu + dot(h[col]) over this warp's 32-col slice ----
    long cbase[2];
#pragma unroll
    for (int rr = 0; rr < 2; rr++)
        cbase[rr] = (long)COL[ebase + rr * 8 + gid] * DDIM;

    float dotp[2] = {0.f, 0.f};
#pragma unroll
    for (int nt = 0; nt < 4; nt++) {
        const int n = nq * 32 + nt * 8 + 2 * tig;
        const float2 s3 = *(const float2*)&S3[n];
        const float2 q3 = *(const float2*)&Q3[n];
#pragma unroll
        for (int rr = 0; rr < 2; rr++) {
            float z0 = fmaxf(fmaf(acc[nt][rr * 2 + 0], s3.x, q3.x), 0.0f);
            float z1 = fmaxf(fmaf(acc[nt][rr * 2 + 1], s3.y, q3.y), 0.0f);
            const float2 c2 = __ldg((const float2*)(h + cbase[rr] + n));
            dotp[rr] = fmaf(z0, c2.x, fmaf(z1, c2.y, dotp[rr]));
        }
    }
    float* dsum = (float*)(smc + DS_OFF);
#pragma unroll
    for (int rr = 0; rr < 2; rr++) {
        float s = dotp[rr];
        s += __shfl_xor_sync(0xffffffffu, s, 1, 4);
        s += __shfl_xor_sync(0xffffffffu, s, 2, 4);
        if (tig == 0)
            dsum[nq * TILE_E + ebase + rr * 8 + gid] = s;
    }
    __syncthreads();
    if (tid < TILE_E) {
        const float* ds = (const float*)(smc + DS_OFF);
        out[e0 + tid] = (ds[tid] + ds[TILE_E + tid]) +
                        (ds[2 * TILE_E + tid] + ds[3 * TILE_E + tid]);
    }
}

// ===== launch =====
extern "C" void kernel_launch(void* const* d_in, const int* in_sizes, int n_in,
                              void* d_out, int out_size)
{
    const float* h      = (const float*)d_in[0];
    const float* g      = (const float*)d_in[1];
    const int*   eidx   = (const int*)d_in[2];
    const int*   etype  = (const int*)d_in[3];
    const float* conv_w = (const float*)d_in[4];
    const float* conv_b = (const float*)d_in[5];
    const float* fc_w   = (const float*)d_in[6];
    const float* fc_b   = (const float*)d_in[7];
    const float* bn1g   = (const float*)d_in[8];
    const float* bn1b   = (const float*)d_in[9];
    const float* bn1m   = (const float*)d_in[10];
    const float* bn1v   = (const float*)d_in[11];
    const float* bn3g   = (const float*)d_in[12];
    const float* bn3b   = (const float*)d_in[13];
    const float* bn3m   = (const float*)d_in[14];
    const float* bn3v   = (const float*)d_in[15];
    float* out = (float*)d_out;

    conve_prep<<<256, 256>>>(fc_w);

    cudaFuncSetAttribute(conve_main,
                         cudaFuncAttributeMaxDynamicSharedMemorySize, SMEM_BYTES);
    conve_main<<<E_TOT / TILE_E, NTHREADS, SMEM_BYTES>>>(
        h, g, eidx, etype, conv_w, conv_b, fc_b,
        bn1g, bn1b, bn1m, bn1v, bn3g, bn3b, bn3m, bn3v, out);
}